// round 5
// baseline (speedup 1.0000x reference)
#include <cuda_runtime.h>
#include <cuda_fp16.h>
#include <cstdint>

// ============================================================================
// PairwiseMLPLinkPredictor — persistent weight-stationary HMMA pipeline.
//   grid = #SMs, 1 CTA/SM, each CTA loops over tiles of 64 pairs.
//   W1 [256x256] fp16 resident in SMEM (swizzled image, loaded once).
//   W2 [256x128] fp16 resident in REGISTERS as mma B-fragments (32/lane).
//   feats double-buffered (2 x 32KB): gather(t+1) overlaps epilogue of t.
//   layer3 fp32 from accumulators + shfl/smem reduce.
// ============================================================================

#define NTH    512
#define TILE_M 64

// ---- SMEM layout (bytes) ----
#define OFF_F0    0         // 32768 : feats/h1 buffer 0  [64][256] f16 swizzled
#define OFF_F1    32768     // 32768 : feats/h1 buffer 1
#define OFF_W1    65536     // 131072: W1^T image [256 n][256 k] f16 swizzled
#define OFF_B1    196608    // 1024  : b1
#define OFF_PART  197632    // 4096  : layer-3 partials [16][64]
#define SMEM_BYTES 201728

// swizzled byte offset inside a [rows][256] fp16 tile (row stride 512B)
__host__ __device__ __forceinline__ uint32_t timg(int r, int k) {
    return (uint32_t)(r * 512 + ((((k >> 3) ^ (r & 7)) & 31) << 4) + ((k & 7) << 1));
}

// ---- global fp16 weight images (prep kernel output) ----
__device__ __align__(1024) unsigned char g_W1h[131072];  // [256][256] swizzled
__device__ __align__(1024) unsigned char g_W2t[65536];   // [128 n][256 k] plain

// ---------------------------------------------------------------------------
__device__ __forceinline__ uint32_t smem_u32(const void* p) {
    uint32_t a;
    asm("{ .reg .u64 t; cvta.to.shared.u64 t, %1; cvt.u32.u64 %0, t; }" : "=r"(a) : "l"(p));
    return a;
}
__device__ __forceinline__ void ldsm_x4(uint32_t r[4], uint32_t addr) {
    asm volatile("ldmatrix.sync.aligned.m8n8.x4.shared.b16 {%0,%1,%2,%3}, [%4];"
                 : "=r"(r[0]), "=r"(r[1]), "=r"(r[2]), "=r"(r[3]) : "r"(addr));
}
__device__ __forceinline__ void mma16816(float c[4], const uint32_t a[4],
                                         uint32_t b0, uint32_t b1) {
    asm volatile("mma.sync.aligned.m16n8k16.row.col.f32.f16.f16.f32 "
                 "{%0,%1,%2,%3}, {%4,%5,%6,%7}, {%8,%9}, {%0,%1,%2,%3};"
                 : "+f"(c[0]), "+f"(c[1]), "+f"(c[2]), "+f"(c[3])
                 : "r"(a[0]), "r"(a[1]), "r"(a[2]), "r"(a[3]), "r"(b0), "r"(b1));
}
#define CP16(dst, src) \
    asm volatile("cp.async.cg.shared.global [%0], [%1], 16;" :: "r"(dst), "l"(src) : "memory")
#define CP_COMMIT() asm volatile("cp.async.commit_group;" ::: "memory")
#define CP_WAIT0()  asm volatile("cp.async.wait_group 0;" ::: "memory")

// ---------------------------------------------------------------------------
// Prep: W1h[n][k] = fp16(W1[k*256+n]) swizzled; W2t[n][k] = fp16(W2[k*128+n]).
// ---------------------------------------------------------------------------
__global__ void prep_kernel(const float* __restrict__ W1, const float* __restrict__ W2) {
    const int i = blockIdx.x * blockDim.x + threadIdx.x;  // 65536
    {
        const int n = i >> 8, k = i & 255;
        *(__half*)(g_W1h + timg(n, k)) = __float2half(W1[k * 256 + n]);
    }
    if (i < 32768) {
        const int n = i >> 8, k = i & 255;
        ((__half*)g_W2t)[n * 256 + k] = __float2half(W2[k * 128 + n]);
    }
}

// ---------------------------------------------------------------------------
__device__ __forceinline__ void gather_tile(char* smem, uint32_t bufOff,
                                            const float* __restrict__ x,
                                            const void* __restrict__ ep, bool is32,
                                            long long e0, int E, int tid)
{
    const int p = tid >> 3, sub = tid & 7;
    const long long e = e0 + p;
    long long ia = 0, ib = 0;
    if (e < (long long)E) {
        if (is32) { ia = ((const int*)ep)[2 * e];       ib = ((const int*)ep)[2 * e + 1]; }
        else      { ia = ((const long long*)ep)[2 * e]; ib = ((const long long*)ep)[2 * e + 1]; }
    }
    const float* xa = x + (size_t)ia * 256;
    const float* xb = x + (size_t)ib * 256;
    const int k0 = sub * 32;
    #pragma unroll
    for (int j = 0; j < 4; j++) {
        float4 a0 = __ldg((const float4*)(xa + k0 + 8 * j));
        float4 a1 = __ldg((const float4*)(xa + k0 + 8 * j + 4));
        float4 c0 = __ldg((const float4*)(xb + k0 + 8 * j));
        float4 c1 = __ldg((const float4*)(xb + k0 + 8 * j + 4));
        union { __half2 h; uint32_t u; } q0, q1, q2, q3;
        q0.h = __floats2half2_rn(a0.x * c0.x, a0.y * c0.y);
        q1.h = __floats2half2_rn(a0.z * c0.z, a0.w * c0.w);
        q2.h = __floats2half2_rn(a1.x * c1.x, a1.y * c1.y);
        q3.h = __floats2half2_rn(a1.z * c1.z, a1.w * c1.w);
        *(uint4*)(smem + bufOff + timg(p, k0 + 8 * j)) = make_uint4(q0.u, q1.u, q2.u, q3.u);
    }
}

// ---------------------------------------------------------------------------
__global__ void __launch_bounds__(NTH, 1)
pairmlp_pers_kernel(const float* __restrict__ x,
                    const float* __restrict__ b1, const float* __restrict__ b2,
                    const float* __restrict__ W3, const float* __restrict__ b3,
                    const void*  __restrict__ ep, float* __restrict__ out,
                    int E, int T)
{
    extern __shared__ char smem[];
    const uint32_t sb = smem_u32(smem);
    const int tid = threadIdx.x, w = tid >> 5, lane = tid & 31;
    const int g = lane >> 2, tig = lane & 3;

    float* sB1 = (float*)(smem + OFF_B1);
    float* sPart = (float*)(smem + OFF_PART);

    // ---- dtype probe: int64 edge_pairs -> odd int32 words of first 1KB all 0 ----
    int probe = 0;
    if (tid < 128) probe = ((const int*)ep)[2 * tid + 1];
    const bool is32 = (__syncthreads_or(probe != 0) != 0);

    // ---- W1 image -> SMEM once (cp.async 128KB) ----
    #pragma unroll
    for (int i = 0; i < 16; i++) {
        const int c = tid + i * NTH;
        CP16(sb + OFF_W1 + c * 16, g_W1h + c * 16);
    }
    CP_COMMIT();

    // ---- W2 B-fragments -> registers once (32 regs/lane) ----
    uint32_t w2f[32];
    {
        const uint32_t* w2t = (const uint32_t*)g_W2t;   // half2 units, row stride 128
        const int n2 = w * 8 + (lane >> 2);
        #pragma unroll
        for (int ks = 0; ks < 16; ks++) {
            w2f[2 * ks]     = w2t[n2 * 128 + 8 * ks + tig];
            w2f[2 * ks + 1] = w2t[n2 * 128 + 8 * ks + 4 + tig];
        }
    }
    // per-lane layer-3 constants
    float2 b2v, w3v;
    {
        const int n0 = w * 8 + 2 * tig;
        b2v = *(const float2*)&b2[n0];
        w3v = *(const float2*)&W3[n0];
    }
    const float b3v = __ldg(b3);
    if (tid < 256) sB1[tid] = b1[tid];

    // ---- gather first tile into buf0 ----
    if (blockIdx.x < (unsigned)T)
        gather_tile(smem, OFF_F0, x, ep, is32, (long long)blockIdx.x * TILE_M, E, tid);
    CP_WAIT0();
    __syncthreads();

    // warp geometry
    const int wm = w & 3, wn = w >> 2;                            // layer-1 4m x 4n
    const int arow0 = wm * 16 + ((lane >> 3) & 1) * 8 + (lane & 7);
    const int acsel = lane >> 4;
    const int brow0 = ((lane >> 4) & 1) * 8 + (lane & 7);
    const int bcsel = (lane >> 3) & 1;
    const uint32_t bB = sb + OFF_W1;

    int cur = 0;
    for (int tile = blockIdx.x; tile < T; tile += gridDim.x) {
        const uint32_t fOff = cur ? OFF_F1 : OFF_F0;
        const uint32_t aB = sb + fOff;
        const long long e0 = (long long)tile * TILE_M;

        // ---------------- layer 1: 64x256x256, warp 16x64 ----------------
        float acc1[8][4];
        #pragma unroll
        for (int ni = 0; ni < 8; ni++)
            #pragma unroll
            for (int v = 0; v < 4; v++) acc1[ni][v] = 0.0f;

        #pragma unroll
        for (int ks = 0; ks < 16; ks++) {
            uint32_t af[4];
            ldsm_x4(af, aB + arow0 * 512 + ((((2 * ks + acsel) ^ (arow0 & 7)) & 31) << 4));
            #pragma unroll
            for (int nb = 0; nb < 4; nb++) {
                const int r = wn * 64 + nb * 16 + brow0;
                uint32_t bf[4];
                ldsm_x4(bf, bB + r * 512 + ((((2 * ks + bcsel) ^ (r & 7)) & 31) << 4));
                mma16816(acc1[nb * 2 + 0], af, bf[0], bf[1]);
                mma16816(acc1[nb * 2 + 1], af, bf[2], bf[3]);
            }
        }
        __syncthreads();        // feats(t) fully consumed

        // ---------------- epilogue 1: h1 -> same buffer ----------------
        {
            const int r0 = wm * 16 + g, r1 = r0 + 8;
            #pragma unroll
            for (int ni = 0; ni < 8; ni++) {
                const int c0 = wn * 64 + ni * 8 + 2 * tig;
                const float2 bb = *(const float2*)&sB1[c0];
                union { __half2 h; uint32_t u; } lo, hi;
                lo.h = __floats2half2_rn(fmaxf(acc1[ni][0] + bb.x, 0.0f),
                                         fmaxf(acc1[ni][1] + bb.y, 0.0f));
                hi.h = __floats2half2_rn(fmaxf(acc1[ni][2] + bb.x, 0.0f),
                                         fmaxf(acc1[ni][3] + bb.y, 0.0f));
                *(uint32_t*)(smem + fOff + timg(r0, c0)) = lo.u;
                *(uint32_t*)(smem + fOff + timg(r1, c0)) = hi.u;
            }
        }
        // ---------------- gather(t+grid) into other buffer ----------------
        {
            const int nxt = tile + gridDim.x;
            if (nxt < T)
                gather_tile(smem, cur ? OFF_F0 : OFF_F1, x, ep, is32,
                            (long long)nxt * TILE_M, E, tid);
        }
        __syncthreads();        // h1 visible (+ next feats staged)

        // ---------------- layer 2: 64x128x256, warp M=64 x N=8 (B in regs) ----
        float acc2[4][4];
        #pragma unroll
        for (int mt = 0; mt < 4; mt++)
            #pragma unroll
            for (int v = 0; v < 4; v++) acc2[mt][v] = 0.0f;

        #pragma unroll
        for (int ks = 0; ks < 16; ks++) {
            #pragma unroll
            for (int mt = 0; mt < 4; mt++) {
                const int r = mt * 16 + ((lane >> 3) & 1) * 8 + (lane & 7);
                uint32_t af[4];
                ldsm_x4(af, aB + r * 512 + ((((2 * ks + acsel) ^ (r & 7)) & 31) << 4));
                mma16816(acc2[mt], af, w2f[2 * ks], w2f[2 * ks + 1]);
            }
        }

        // ---------------- layer 3: reduce + store ----------------
        #pragma unroll
        for (int mt = 0; mt < 4; mt++) {
            float s0 = fmaxf(acc2[mt][0] + b2v.x, 0.0f) * w3v.x
                     + fmaxf(acc2[mt][1] + b2v.y, 0.0f) * w3v.y;
            float s1 = fmaxf(acc2[mt][2] + b2v.x, 0.0f) * w3v.x
                     + fmaxf(acc2[mt][3] + b2v.y, 0.0f) * w3v.y;
            s0 += __shfl_xor_sync(0xffffffffu, s0, 1);
            s0 += __shfl_xor_sync(0xffffffffu, s0, 2);
            s1 += __shfl_xor_sync(0xffffffffu, s1, 1);
            s1 += __shfl_xor_sync(0xffffffffu, s1, 2);
            if (tig == 0) {
                sPart[w * 64 + mt * 16 + g]     = s0;
                sPart[w * 64 + mt * 16 + 8 + g] = s1;
            }
        }
        __syncthreads();
        if (tid < 64) {
            const long long e = e0 + tid;
            if (e < E) {
                float s = b3v;
                #pragma unroll
                for (int ww = 0; ww < 16; ww++) s += sPart[ww * 64 + tid];
                out[e] = s;
            }
        }
        __syncthreads();        // sPart + buffers free for next iteration
        cur ^= 1;
    }
}

// ---------------------------------------------------------------------------
extern "C" void kernel_launch(void* const* d_in, const int* in_sizes, int n_in,
                              void* d_out, int out_size)
{
    const float* x  = (const float*)d_in[0];
    const float* W1 = (const float*)d_in[1];
    const float* b1 = (const float*)d_in[2];
    const float* W2 = (const float*)d_in[3];
    const float* b2 = (const float*)d_in[4];
    const float* W3 = (const float*)d_in[5];
    const float* b3 = (const float*)d_in[6];
    // d_in[7] = edge_index (unused)
    const void*  ep = d_in[8];
    float* out = (float*)d_out;

    const int E = out_size;
    const int T = (E + TILE_M - 1) / TILE_M;

    prep_kernel<<<256, 256>>>(W1, W2);

    int dev = 0, sms = 148;
    cudaGetDevice(&dev);
    cudaDeviceGetAttribute(&sms, cudaDevAttrMultiProcessorCount, dev);
    int grid = sms < T ? sms : T;

    cudaFuncSetAttribute(pairmlp_pers_kernel,
                         cudaFuncAttributeMaxDynamicSharedMemorySize, SMEM_BYTES);
    pairmlp_pers_kernel<<<grid, NTH, SMEM_BYTES>>>(x, b1, b2, W3, b3, ep, out, E, T);
}

// round 6
// speedup vs baseline: 1.6021x; 1.6021x over previous
#include <cuda_runtime.h>
#include <cuda_fp16.h>
#include <cstdint>

// ============================================================================
// PairwiseMLPLinkPredictor — HMMA, 2 CTAs/SM phase-overlap version.
//   TILE 64 pairs/CTA, 8 warps, smem ~101KB -> 2 CTA/SM.
//   W1 [256n][256k] fp16 streamed as 4 swizzled 32KB k-slices (cp.async dbuf).
//   W2 [128n][256k] fp16 as 4 swizzled 16KB k-slices, fetched in epilogue 1.
//   layer tiles: L1 warp 32x64 (6 ldsm / 16 mma), L2 warp 32x32 (4 / 8).
// ============================================================================

#define NTH    256
#define TILE_M 64

// ---- SMEM layout (bytes) ----
#define OFF_FEATS 0          // 32768 : feats/h1 [64][256] f16 swizzled (512B rows)
#define OFF_WS0   32768      // 32768 : weight slice buffer 0
#define OFF_WS1   65536      // 32768 : weight slice buffer 1
#define OFF_IDX   98304      // 1024  : 128 x int64
#define OFF_B1    99328      // 1024
#define OFF_B2    100352     // 512
#define OFF_W3    100864     // 512
#define OFF_PART  101376     // 1024  : layer-3 partials [4][64]
#define SMEM_BYTES 102400

// swizzled offset in a [rows][256] fp16 tile (512B rows, 32 chunks of 16B)
__host__ __device__ __forceinline__ uint32_t timg(int r, int k) {
    return (uint32_t)(r * 512 + ((((k >> 3) ^ (r & 7)) & 31) << 4) + ((k & 7) << 1));
}
// swizzled offset in a [rows][64] fp16 slice (128B rows, 8 chunks of 16B)
__host__ __device__ __forceinline__ uint32_t timg64(int r, int k) {
    return (uint32_t)(r * 128 + ((((k >> 3) ^ (r & 7)) & 7) << 4) + ((k & 7) << 1));
}

// ---- global fp16 weight slice images (prep kernel output) ----
__device__ __align__(1024) unsigned char g_W1s[131072]; // 4 slices [256n][64k]
__device__ __align__(1024) unsigned char g_W2s[65536];  // 4 slices [128n][64k]

// ---------------------------------------------------------------------------
__device__ __forceinline__ uint32_t smem_u32(const void* p) {
    uint32_t a;
    asm("{ .reg .u64 t; cvta.to.shared.u64 t, %1; cvt.u32.u64 %0, t; }" : "=r"(a) : "l"(p));
    return a;
}
__device__ __forceinline__ void ldsm_x4(uint32_t r[4], uint32_t addr) {
    asm volatile("ldmatrix.sync.aligned.m8n8.x4.shared.b16 {%0,%1,%2,%3}, [%4];"
                 : "=r"(r[0]), "=r"(r[1]), "=r"(r[2]), "=r"(r[3]) : "r"(addr));
}
__device__ __forceinline__ void mma16816(float c[4], const uint32_t a[4],
                                         uint32_t b0, uint32_t b1) {
    asm volatile("mma.sync.aligned.m16n8k16.row.col.f32.f16.f16.f32 "
                 "{%0,%1,%2,%3}, {%4,%5,%6,%7}, {%8,%9}, {%0,%1,%2,%3};"
                 : "+f"(c[0]), "+f"(c[1]), "+f"(c[2]), "+f"(c[3])
                 : "r"(a[0]), "r"(a[1]), "r"(a[2]), "r"(a[3]), "r"(b0), "r"(b1));
}
#define CP16(dst, src) \
    asm volatile("cp.async.cg.shared.global [%0], [%1], 16;" :: "r"(dst), "l"(src) : "memory")
#define CP_COMMIT() asm volatile("cp.async.commit_group;" ::: "memory")
#define CP_WAIT(n)  asm volatile("cp.async.wait_group %0;" :: "n"(n) : "memory")

// ---------------------------------------------------------------------------
// Prep: slice, transpose, fp16-quantize, swizzle.
// W1s[s][n][kk] = fp16(W1[(s*64+kk)*256+n]); W2s likewise from W2 [256,128].
// ---------------------------------------------------------------------------
__global__ void prep_kernel(const float* __restrict__ W1, const float* __restrict__ W2) {
    const int i = blockIdx.x * blockDim.x + threadIdx.x;  // 65536
    {
        const int n = i >> 8, k = i & 255;
        *(__half*)(g_W1s + (k >> 6) * 32768 + timg64(n, k & 63)) =
            __float2half(W1[k * 256 + n]);
    }
    if (i < 32768) {
        const int n = i >> 8, k = i & 255;      // n<128
        *(__half*)(g_W2s + (k >> 6) * 16384 + timg64(n, k & 63)) =
            __float2half(W2[k * 128 + n]);
    }
}

// ---------------------------------------------------------------------------
__global__ void __launch_bounds__(NTH, 2)
pairmlp_hmma2_kernel(const float* __restrict__ x,
                     const float* __restrict__ b1, const float* __restrict__ b2,
                     const float* __restrict__ W3, const float* __restrict__ b3,
                     const void*  __restrict__ ep, float* __restrict__ out, int E)
{
    extern __shared__ char smem[];
    const uint32_t sb = smem_u32(smem);
    const int tid = threadIdx.x, w = tid >> 5, lane = tid & 31;
    const int g = lane >> 2, tig = lane & 3;
    const long long e0 = (long long)blockIdx.x * TILE_M;

    long long* sIdx = (long long*)(smem + OFF_IDX);
    float* sB1 = (float*)(smem + OFF_B1);
    float* sB2 = (float*)(smem + OFF_B2);
    float* sW3 = (float*)(smem + OFF_W3);
    float* sPart = (float*)(smem + OFF_PART);

    // ---- dtype probe: int64 edge_pairs -> odd int32 words of first 1KB all 0 ----
    int probe = 0;
    if (tid < 128) probe = ((const int*)ep)[2 * tid + 1];
    const bool is32 = (__syncthreads_or(probe != 0) != 0);

    // ---- kick W1 slice0 -> WS0 (group0), slice1 -> WS1 (group1) ----
    #pragma unroll
    for (int i = 0; i < 8; i++) {
        const int c = tid + i * NTH;                       // 2048 chunks
        CP16(sb + OFF_WS0 + c * 16, g_W1s + c * 16);
    }
    CP_COMMIT();
    #pragma unroll
    for (int i = 0; i < 8; i++) {
        const int c = tid + i * NTH;
        CP16(sb + OFF_WS1 + c * 16, g_W1s + 32768 + c * 16);
    }
    CP_COMMIT();

    // ---- indices + small vectors ----
    if (tid < 128) {
        long long gi = 2 * e0 + tid, v = 0;
        if (gi < 2LL * E) v = is32 ? (long long)((const int*)ep)[gi] : ((const long long*)ep)[gi];
        sIdx[tid] = v;
    }
    sB1[tid] = b1[tid];
    if (tid < 128) { sB2[tid] = b2[tid]; sW3[tid] = W3[tid]; }
    __syncthreads();

    // ---- gather + product -> fp16 feats (swizzled) ----
    {
        const int p = tid >> 2, q = tid & 3;
        const float* xa = x + (size_t)sIdx[2 * p] * 256;
        const float* xb = x + (size_t)sIdx[2 * p + 1] * 256;
        #pragma unroll
        for (int j = 0; j < 8; j++) {
            const int k0 = q * 64 + j * 8;
            float4 a0 = __ldg((const float4*)(xa + k0));
            float4 a1 = __ldg((const float4*)(xa + k0 + 4));
            float4 c0 = __ldg((const float4*)(xb + k0));
            float4 c1 = __ldg((const float4*)(xb + k0 + 4));
            union { __half2 h; uint32_t u; } q0, q1, q2, q3;
            q0.h = __floats2half2_rn(a0.x * c0.x, a0.y * c0.y);
            q1.h = __floats2half2_rn(a0.z * c0.z, a0.w * c0.w);
            q2.h = __floats2half2_rn(a1.x * c1.x, a1.y * c1.y);
            q3.h = __floats2half2_rn(a1.z * c1.z, a1.w * c1.w);
            *(uint4*)(smem + OFF_FEATS + timg(p, k0)) = make_uint4(q0.u, q1.u, q2.u, q3.u);
        }
    }

    // warp geometry
    const int wm = w & 1, wn = w >> 1;                 // L1: 2m x 4n (warp 32x64)
    const int arow0 = ((lane >> 3) & 1) * 8 + (lane & 7);
    const int acsel = lane >> 4;
    const int brow0 = ((lane >> 4) & 1) * 8 + (lane & 7);
    const int bcsel = (lane >> 3) & 1;
    const uint32_t aB = sb + OFF_FEATS;

    // ================= layer 1: 64x256x256, warp 32x64 =================
    float acc1[2][8][4];
    #pragma unroll
    for (int mi = 0; mi < 2; mi++)
        #pragma unroll
        for (int ni = 0; ni < 8; ni++)
            #pragma unroll
            for (int v = 0; v < 4; v++) acc1[mi][ni][v] = 0.0f;

    CP_WAIT(1);            // slice0 landed
    __syncthreads();       // + feats staged

    #pragma unroll
    for (int s = 0; s < 4; s++) {
        const uint32_t bB = sb + ((s & 1) ? OFF_WS1 : OFF_WS0);
        #pragma unroll
        for (int ksl = 0; ksl < 4; ksl++) {
            const int ks = s * 4 + ksl;
            uint32_t af[2][4];
            #pragma unroll
            for (int mi = 0; mi < 2; mi++) {
                const int r = wm * 32 + mi * 16 + arow0;
                ldsm_x4(af[mi], aB + r * 512 + ((((2 * ks + acsel) ^ (r & 7)) & 31) << 4));
            }
            #pragma unroll
            for (int nb = 0; nb < 4; nb++) {
                const int r = wn * 64 + nb * 16 + brow0;
                uint32_t bf[4];
                ldsm_x4(bf, bB + r * 128 + ((((2 * ksl + bcsel) ^ (r & 7)) & 7) << 4));
                #pragma unroll
                for (int mi = 0; mi < 2; mi++) {
                    mma16816(acc1[mi][nb * 2 + 0], af[mi], bf[0], bf[1]);
                    mma16816(acc1[mi][nb * 2 + 1], af[mi], bf[2], bf[3]);
                }
            }
        }
        if (s < 2) {
            __syncthreads();                 // all warps done with this buffer
            #pragma unroll
            for (int i = 0; i < 8; i++) {    // stream W1 slice s+2 into it
                const int c = tid + i * NTH;
                CP16(sb + ((s & 1) ? OFF_WS1 : OFF_WS0) + c * 16,
                     g_W1s + (s + 2) * 32768 + c * 16);
            }
            CP_COMMIT();
            CP_WAIT(1);                      // next slice (s+1) landed
            __syncthreads();
        } else if (s == 2) {
            CP_WAIT(0);                      // slice3 landed
        }
    }
    __syncthreads();       // layer-1 reads of feats + WS1 complete

    // ---- kick W2 (4 slices, 64KB) into WS0(+WS1); overlap epilogue 1 ----
    #pragma unroll
    for (int i = 0; i < 16; i++) {
        const int c = tid + i * NTH;         // 4096 chunks; WS0..WS1 contiguous
        CP16(sb + OFF_WS0 + c * 16, g_W2s + c * 16);
    }
    CP_COMMIT();

    // ---- epilogue 1: h1 = fp16(relu(acc1 + b1)) -> feats buffer ----
    #pragma unroll
    for (int mi = 0; mi < 2; mi++) {
        const int r0 = wm * 32 + mi * 16 + g, r1 = r0 + 8;
        #pragma unroll
        for (int ni = 0; ni < 8; ni++) {
            const int c0 = wn * 64 + ni * 8 + 2 * tig;
            const float2 bb = *(const float2*)&sB1[c0];
            union { __half2 h; uint32_t u; } lo, hi;
            lo.h = __floats2half2_rn(fmaxf(acc1[mi][ni][0] + bb.x, 0.0f),
                                     fmaxf(acc1[mi][ni][1] + bb.y, 0.0f));
            hi.h = __floats2half2_rn(fmaxf(acc1[mi][ni][2] + bb.x, 0.0f),
                                     fmaxf(acc1[mi][ni][3] + bb.y, 0.0f));
            *(uint32_t*)(smem + OFF_FEATS + timg(r0, c0)) = lo.u;
            *(uint32_t*)(smem + OFF_FEATS + timg(r1, c0)) = hi.u;
        }
    }
    CP_WAIT(0);
    __syncthreads();

    // ================= layer 2: 64x128x256, warp 32x32 =================
    const int wm2 = w & 1, wn2 = w >> 1;               // 2m x 4n
    float acc2[2][4][4];
    #pragma unroll
    for (int mi = 0; mi < 2; mi++)
        #pragma unroll
        for (int ni = 0; ni < 4; ni++)
            #pragma unroll
            for (int v = 0; v < 4; v++) acc2[mi][ni][v] = 0.0f;

    #pragma unroll
    for (int ks = 0; ks < 16; ks++) {
        const uint32_t bB = sb + OFF_WS0 + (ks >> 2) * 16384;
        const int ksl = ks & 3;
        uint32_t af[2][4];
        #pragma unroll
        for (int mi = 0; mi < 2; mi++) {
            const int r = wm2 * 32 + mi * 16 + arow0;
            ldsm_x4(af[mi], aB + r * 512 + ((((2 * ks + acsel) ^ (r & 7)) & 31) << 4));
        }
        #pragma unroll
        for (int nb = 0; nb < 2; nb++) {
            const int r = wn2 * 32 + nb * 16 + brow0;
            uint32_t bf[4];
            ldsm_x4(bf, bB + r * 128 + ((((2 * ksl + bcsel) ^ (r & 7)) & 7) << 4));
            #pragma unroll
            for (int mi = 0; mi < 2; mi++) {
                mma16816(acc2[mi][nb * 2 + 0], af[mi], bf[0], bf[1]);
                mma16816(acc2[mi][nb * 2 + 1], af[mi], bf[2], bf[3]);
            }
        }
    }

    // ---- layer 3: out = relu(D2 + b2) . W3 + b3 ----
    #pragma unroll
    for (int mi = 0; mi < 2; mi++) {
        float s0 = 0.0f, s1 = 0.0f;
        #pragma unroll
        for (int ni = 0; ni < 4; ni++) {
            const int c0 = wn2 * 32 + ni * 8 + 2 * tig;
            const float2 bb = *(const float2*)&sB2[c0];
            const float2 ww = *(const float2*)&sW3[c0];
            s0 += fmaxf(acc2[mi][ni][0] + bb.x, 0.0f) * ww.x
                + fmaxf(acc2[mi][ni][1] + bb.y, 0.0f) * ww.y;
            s1 += fmaxf(acc2[mi][ni][2] + bb.x, 0.0f) * ww.x
                + fmaxf(acc2[mi][ni][3] + bb.y, 0.0f) * ww.y;
        }
        s0 += __shfl_xor_sync(0xffffffffu, s0, 1);
        s0 += __shfl_xor_sync(0xffffffffu, s0, 2);
        s1 += __shfl_xor_sync(0xffffffffu, s1, 1);
        s1 += __shfl_xor_sync(0xffffffffu, s1, 2);
        if (tig == 0) {
            const int r0 = wm2 * 32 + mi * 16 + g;
            sPart[wn2 * 64 + r0]     = s0;
            sPart[wn2 * 64 + r0 + 8] = s1;
        }
    }
    __syncthreads();

    if (tid < 64) {
        const long long e = e0 + tid;
        if (e < E)
            out[e] = sPart[tid] + sPart[64 + tid] + sPart[128 + tid] + sPart[192 + tid]
                   + __ldg(b3);
    }
}

// ---------------------------------------------------------------------------
extern "C" void kernel_launch(void* const* d_in, const int* in_sizes, int n_in,
                              void* d_out, int out_size)
{
    const float* x  = (const float*)d_in[0];
    const float* W1 = (const float*)d_in[1];
    const float* b1 = (const float*)d_in[2];
    const float* W2 = (const float*)d_in[3];
    const float* b2 = (const float*)d_in[4];
    const float* W3 = (const float*)d_in[5];
    const float* b3 = (const float*)d_in[6];
    // d_in[7] = edge_index (unused)
    const void*  ep = d_in[8];
    float* out = (float*)d_out;

    const int E = out_size;
    prep_kernel<<<256, 256>>>(W1, W2);

    cudaFuncSetAttribute(pairmlp_hmma2_kernel,
                         cudaFuncAttributeMaxDynamicSharedMemorySize, SMEM_BYTES);
    const int nblocks = (E + TILE_M - 1) / TILE_M;
    pairmlp_hmma2_kernel<<<nblocks, NTH, SMEM_BYTES>>>(x, b1, b2, W3, b3, ep, out, E);
}